// round 7
// baseline (speedup 1.0000x reference)
#include <cuda_runtime.h>

#define N_FULL 50000
#define NLAT 10
#define MU 32
#define BATCH 8
#define TILE 16
#define ENC_CHUNKS 25
#define ENC_VPC 500         // float4 per chunk (25*500 = 12500 = N/4)
#define ENC_BLOCKS (ENC_CHUNKS * BATCH)     // 200
#define PREP_BLOCKS ((N_FULL + 255) / 256)  // 196

// Scratch (allocation-free rule: __device__ globals)
__device__ float  g_part[ENC_CHUNKS * BATCH * NLAT];  // [chunk][b*10+i] partial dots
__device__ float4 g_dect[N_FULL * 4];   // [node][4 x float4]: 10 decoder vals + pad

// ---------------------------------------------------------------------------
// Kernel 1 (fused): blocks [0,200) encode split-K partials (no atomics);
// blocks [200,396) transpose decoder into g_dect.
// ---------------------------------------------------------------------------
__global__ __launch_bounds__(256)
void encprep_kernel(const float* __restrict__ x,
                    const float* __restrict__ ew,
                    const float* __restrict__ dec) {
    int bid = blockIdx.x;
    int tid = threadIdx.x;

    if (bid < ENC_BLOCKS) {
        int b     = bid / ENC_CHUNKS;
        int chunk = bid % ENC_CHUNKS;
        int c0    = chunk * ENC_VPC;
        int t0 = tid, t1 = tid + 256;

        const float4* xv = (const float4*)(x + (size_t)b * N_FULL) + c0;
        float4 xa = xv[t0];
        float4 xb = (t1 < ENC_VPC) ? xv[t1] : make_float4(0.f, 0.f, 0.f, 0.f);

        float acc[NLAT];
        #pragma unroll
        for (int i = 0; i < NLAT; i++) {
            const float4* wv = (const float4*)(ew + (size_t)i * N_FULL) + c0;
            float4 wa = wv[t0];
            float4 wb = (t1 < ENC_VPC) ? wv[t1] : make_float4(0.f, 0.f, 0.f, 0.f);
            float s;
            s = xa.x * wa.x;
            s = fmaf(xa.y, wa.y, s);
            s = fmaf(xa.z, wa.z, s);
            s = fmaf(xa.w, wa.w, s);
            s = fmaf(xb.x, wb.x, s);
            s = fmaf(xb.y, wb.y, s);
            s = fmaf(xb.z, wb.z, s);
            s = fmaf(xb.w, wb.w, s);
            acc[i] = s;
        }

        __shared__ float red[8][NLAT];
        #pragma unroll
        for (int i = 0; i < NLAT; i++) {
            float s = acc[i];
            #pragma unroll
            for (int o = 16; o; o >>= 1) s += __shfl_down_sync(0xffffffffu, s, o);
            if ((tid & 31) == 0) red[tid >> 5][i] = s;
        }
        __syncthreads();
        if (tid < NLAT) {
            float s = 0.f;
            #pragma unroll
            for (int w = 0; w < 8; w++) s += red[w][tid];
            g_part[chunk * (BATCH * NLAT) + b * NLAT + tid] = s;
        }
    } else {
        int j = (bid - ENC_BLOCKS) * 256 + tid;
        if (j >= N_FULL) return;
        float d[NLAT];
        #pragma unroll
        for (int i = 0; i < NLAT; i++) d[i] = dec[(size_t)i * N_FULL + j];
        g_dect[j * 4 + 0] = make_float4(d[0], d[1], d[2], d[3]);
        g_dect[j * 4 + 1] = make_float4(d[4], d[5], d[6], d[7]);
        g_dect[j * 4 + 2] = make_float4(d[8], d[9], 0.f, 0.f);
    }
}

// ---------------------------------------------------------------------------
// Kernel 2: main. Per block: TILE=16 nodes, 256 threads, 5 blocks/SM.
//   E: reduce encode partials (80 threads x 25 batched L2 loads + bias)
//   A: stage neighbour indices (coalesced)
//   B: cooperative gather — 3 lanes share one 64B decoder row (1 L1 line)
//   C: prefix sums over m via register-batched rounds (breaks LDS chain)
//   D: per (node,b,i-half): w=sigmoid(enc.bw) via __ldg; closed-form window
// ---------------------------------------------------------------------------
__global__ __launch_bounds__(256, 5)
void main_kernel(const float* __restrict__ bw,
                 const int*  __restrict__ nb,
                 const float* __restrict__ eb,
                 float*      __restrict__ out) {
    __shared__ float enc_s[BATCH * NLAT];
    __shared__ int   nbs[TILE * MU];          // 2KB; reused as float[256] for D-reduce
    __shared__ float P0s[TILE * NLAT * 33];   // [pl][i][m], stride 33
    __shared__ float P2s[TILE * NLAT * 33];

    int tid = threadIdx.x;
    int p0  = blockIdx.x * TILE;

    // ---- Phase E: per-block encode reduction (batched independent loads) ----
    if (tid < BATCH * NLAT) {
        float s = __ldg(&eb[tid - (tid / NLAT) * NLAT]);
        #pragma unroll
        for (int c = 0; c < ENC_CHUNKS; c++)
            s += g_part[c * (BATCH * NLAT) + tid];
        enc_s[tid] = s;
    }

    // ---- Phase A: stage indices (512 = 2 per thread) ----
    nbs[tid]       = __ldg(&nb[(size_t)p0 * MU + tid]);
    nbs[tid + 256] = __ldg(&nb[(size_t)p0 * MU + tid + 256]);
    __syncthreads();

    // ---- Phase B: cooperative gather (3 lanes per index -> 1 line) ----
    #pragma unroll
    for (int it = 0; it < TILE * MU * 3 / 256; it++) {
        int t = it * 256 + tid;
        int s = t / 3;                 // index id (0..511)
        int chunk = t - s * 3;         // 0,1,2
        int j = nbs[s];
        float4 v = g_dect[j * 4 + chunk];
        int base = (s >> 5) * (NLAT * 33) + (s & 31) + chunk * 132;
        P0s[base]      = v.x;
        P0s[base + 33] = v.y;
        if (chunk != 2) {
            P0s[base + 66] = v.z;
            P0s[base + 99] = v.w;
        }
    }
    __syncthreads();

    // ---- Phase C: prefix sums, register-batched in rounds of 8 ----
    if (tid < TILE * NLAT) {
        int base = tid * 33;
        float s0 = 0.f, s2 = 0.f;
        #pragma unroll
        for (int h = 0; h < 4; h++) {
            float g[8];
            #pragma unroll
            for (int q = 0; q < 8; q++) g[q] = P0s[base + h * 8 + q];  // batched
            #pragma unroll
            for (int q = 0; q < 8; q++) {
                int m = h * 8 + q;
                s0 += g[q];
                s2 = fmaf(g[q], (float)(m * m), s2);
                P0s[base + m] = s0;
                P2s[base + m] = s2;
            }
        }
    }
    __syncthreads();

    // ---- Phase D: 256 threads = 16 nodes x 8 b x 2 i-halves ----
    float* redf = (float*)nbs;
    {
        int b    = tid & 7;
        int pl   = (tid >> 3) & 15;
        int half = tid >> 7;
        int p    = p0 + pl;
        float eb_[NLAT];
        #pragma unroll
        for (int k = 0; k < NLAT; k++) eb_[k] = enc_s[b * NLAT + k];

        const float* bwp = bw + (size_t)half * 5 * NLAT * N_FULL + p;
        float acc = 0.f;
        #pragma unroll
        for (int ii = 0; ii < 5; ii++) {
            int i = half * 5 + ii;
            float t = 0.f;
            #pragma unroll
            for (int k = 0; k < NLAT; k++)
                t = fmaf(eb_[k], __ldg(&bwp[(size_t)(ii * NLAT + k) * N_FULL]), t);
            float w = 1.f / (1.f + __expf(-t));
            float u = fmaxf(32.f * w, 1e-6f);      // 32*w (window cutoff)
            float cinv = __fdividef(1.f, u * u);   // 1/(32w)^2
            int K = min(MU, (int)u + 1);           // #window terms
            float S2K = (float)((K - 1) * K * (2 * K - 1)) * (1.f / 6.f);
            int idx = (pl * NLAT + i) * 33 + (K - 1);
            float P0 = P0s[idx];
            float P2 = P2s[idx];
            float norm = (float)K - cinv * S2K;
            float sm = __fdividef(P0 - cinv * P2, norm);
            acc = fmaf(eb_[i], sm, acc);
        }
        redf[tid] = acc;
    }
    __syncthreads();
    if (tid < 128) {
        int b  = tid & 7;
        int pl = tid >> 3;
        out[(size_t)b * N_FULL + p0 + pl] = redf[tid] + redf[tid + 128];
    }
}

// ---------------------------------------------------------------------------
extern "C" void kernel_launch(void* const* d_in, const int* in_sizes, int n_in,
                              void* d_out, int out_size) {
    const float* x   = (const float*)d_in[0];
    const float* ew  = (const float*)d_in[1];
    const float* ebv = (const float*)d_in[2];
    const float* dec = (const float*)d_in[3];
    const float* bw  = (const float*)d_in[4];
    const int*   nb  = (const int*)d_in[5];
    float* out = (float*)d_out;

    encprep_kernel<<<ENC_BLOCKS + PREP_BLOCKS, 256>>>(x, ew, dec);
    main_kernel<<<N_FULL / TILE, 256>>>(bw, nb, ebv, out);
}

// round 8
// speedup vs baseline: 1.0491x; 1.0491x over previous
#include <cuda_runtime.h>

#define N_FULL 50000
#define NLAT 10
#define MU 32
#define BATCH 8
#define TILE 8
#define MS 35               // m-stride per (pl,i) row  (35 ≡ 3 mod 32)
#define ENC_CHUNKS 25
#define ENC_VPC 500         // float4 per chunk (25*500 = 12500 = N/4)
#define ENC_BLOCKS (ENC_CHUNKS * BATCH)     // 200
#define PREP_BLOCKS ((N_FULL + 255) / 256)  // 196

// Scratch (allocation-free rule: __device__ globals)
__device__ float  g_part[ENC_CHUNKS * BATCH * NLAT];  // [chunk][b*10+i] partial dots
__device__ float4 g_dect[N_FULL * 4];   // [node][4 x float4]: 10 decoder vals + pad

// ---------------------------------------------------------------------------
// Kernel 1 (fused): blocks [0,200) encode split-K partials (no atomics);
// blocks [200,396) transpose decoder into g_dect.
// ---------------------------------------------------------------------------
__global__ __launch_bounds__(256)
void encprep_kernel(const float* __restrict__ x,
                    const float* __restrict__ ew,
                    const float* __restrict__ dec) {
    int bid = blockIdx.x;
    int tid = threadIdx.x;

    if (bid < ENC_BLOCKS) {
        int b     = bid / ENC_CHUNKS;
        int chunk = bid % ENC_CHUNKS;
        int c0    = chunk * ENC_VPC;
        int t0 = tid, t1 = tid + 256;

        const float4* xv = (const float4*)(x + (size_t)b * N_FULL) + c0;
        float4 xa = xv[t0];
        float4 xb = (t1 < ENC_VPC) ? xv[t1] : make_float4(0.f, 0.f, 0.f, 0.f);

        float acc[NLAT];
        #pragma unroll
        for (int i = 0; i < NLAT; i++) {
            const float4* wv = (const float4*)(ew + (size_t)i * N_FULL) + c0;
            float4 wa = wv[t0];
            float4 wb = (t1 < ENC_VPC) ? wv[t1] : make_float4(0.f, 0.f, 0.f, 0.f);
            float s;
            s = xa.x * wa.x;
            s = fmaf(xa.y, wa.y, s);
            s = fmaf(xa.z, wa.z, s);
            s = fmaf(xa.w, wa.w, s);
            s = fmaf(xb.x, wb.x, s);
            s = fmaf(xb.y, wb.y, s);
            s = fmaf(xb.z, wb.z, s);
            s = fmaf(xb.w, wb.w, s);
            acc[i] = s;
        }

        __shared__ float red[8][NLAT];
        #pragma unroll
        for (int i = 0; i < NLAT; i++) {
            float s = acc[i];
            #pragma unroll
            for (int o = 16; o; o >>= 1) s += __shfl_down_sync(0xffffffffu, s, o);
            if ((tid & 31) == 0) red[tid >> 5][i] = s;
        }
        __syncthreads();
        if (tid < NLAT) {
            float s = 0.f;
            #pragma unroll
            for (int w = 0; w < 8; w++) s += red[w][tid];
            g_part[chunk * (BATCH * NLAT) + b * NLAT + tid] = s;
        }
    } else {
        int j = (bid - ENC_BLOCKS) * 256 + tid;
        if (j >= N_FULL) return;
        float d[NLAT];
        #pragma unroll
        for (int i = 0; i < NLAT; i++) d[i] = dec[(size_t)i * N_FULL + j];
        g_dect[j * 4 + 0] = make_float4(d[0], d[1], d[2], d[3]);
        g_dect[j * 4 + 1] = make_float4(d[4], d[5], d[6], d[7]);
        g_dect[j * 4 + 2] = make_float4(d[8], d[9], 0.f, 0.f);
    }
}

// ---------------------------------------------------------------------------
// Kernel 2: main. Per block: TILE=8 nodes, 128 threads, ~9 blocks/SM.
//   E: reduce encode partials (80 threads x 25 batched L2 loads + bias)
//   A: stage neighbour indices via int4 (coalesced)
//   B: cooperative gather — 3 lanes share one 64B decoder row (1 L1 line)
//   C: prefix sums over m (register-batched rounds of 8)
//   D: per (node,b,i-half): 3-MUFU closed-form window via K lookup
// ---------------------------------------------------------------------------
__global__ __launch_bounds__(128)
void main_kernel(const float* __restrict__ bw,
                 const int*  __restrict__ nb,
                 const float* __restrict__ eb,
                 float*      __restrict__ out) {
    __shared__ float enc_s[BATCH * NLAT];
    __shared__ int   nbs[TILE * MU];          // 1KB; reused as float[256] for D-reduce
    __shared__ float P0s[TILE * NLAT * MS];   // [pl][i][m], m-stride 35
    __shared__ float P2s[TILE * NLAT * MS];

    int tid = threadIdx.x;
    int p0  = blockIdx.x * TILE;

    // ---- Phase E: per-block encode reduction (independent batched loads) ----
    if (tid < BATCH * NLAT) {
        float s = __ldg(&eb[tid - (tid / NLAT) * NLAT]);
        #pragma unroll
        for (int c = 0; c < ENC_CHUNKS; c++)
            s += g_part[c * (BATCH * NLAT) + tid];
        enc_s[tid] = s;
    }

    // ---- Phase A: stage indices (256 ints = 64 int4) ----
    if (tid < TILE * MU / 4)
        ((int4*)nbs)[tid] = __ldg(&((const int4*)(nb + (size_t)p0 * MU))[tid]);
    __syncthreads();

    // ---- Phase B: cooperative gather (3 lanes per index -> 1 line) ----
    #pragma unroll
    for (int it = 0; it < TILE * MU * 3 / 128; it++) {   // 6 iters
        int t = it * 128 + tid;
        int s = t / 3;                 // index id (0..255)
        int chunk = t - s * 3;         // 0,1,2
        int j = nbs[s];
        float4 v = g_dect[j * 4 + chunk];
        // row (pl, i=4*chunk+c), element m:  pl*10*MS + (4*chunk+c)*MS + m
        int base = (s >> 5) * (NLAT * MS) + (s & 31) + chunk * (4 * MS);
        P0s[base]          = v.x;
        P0s[base + MS]     = v.y;
        if (chunk != 2) {
            P0s[base + 2 * MS] = v.z;
            P0s[base + 3 * MS] = v.w;
        }
    }
    __syncthreads();

    // ---- Phase C: prefix sums, register-batched in rounds of 8 (80 rows) ----
    if (tid < TILE * NLAT) {
        int base = tid * MS;
        float s0 = 0.f, s2 = 0.f;
        #pragma unroll
        for (int h = 0; h < 4; h++) {
            float g[8];
            #pragma unroll
            for (int q = 0; q < 8; q++) g[q] = P0s[base + h * 8 + q];  // batched
            #pragma unroll
            for (int q = 0; q < 8; q++) {
                int m = h * 8 + q;
                s0 += g[q];
                s2 = fmaf(g[q], (float)(m * m), s2);
                P0s[base + m] = s0;
                P2s[base + m] = s2;
            }
        }
    }
    __syncthreads();

    // ---- Phase D: 128 threads = 8 nodes x 8 b x 2 i-halves ----
    float* redf = (float*)nbs;
    {
        int b    = tid & 7;
        int pl   = (tid >> 3) & 7;
        int half = tid >> 6;
        int p    = p0 + pl;
        float eb_[NLAT];
        #pragma unroll
        for (int k = 0; k < NLAT; k++) eb_[k] = enc_s[b * NLAT + k];

        const float* bwp = bw + (size_t)half * 5 * NLAT * N_FULL + p;
        float acc = 0.f;
        #pragma unroll
        for (int ii = 0; ii < 5; ii++) {
            int i = half * 5 + ii;
            float t = 0.f;
            #pragma unroll
            for (int k = 0; k < NLAT; k++)
                t = fmaf(eb_[k], __ldg(&bwp[(size_t)(ii * NLAT + k) * N_FULL]), t);
            // q = 1/w = 1+e^-t ;  u = 32w = 32/q ;  cinv = 1/u^2 = q^2/1024
            float q = 1.f + __expf(-t);                   // MUFU 1
            float u = __fdividef(32.f, q);                // MUFU 2
            float cinv = q * q * (1.f / 1024.f);
            int K = min(MU, (int)u + 1);                  // #window terms
            float S2K = (float)((K - 1) * K * (2 * K - 1)) * (1.f / 6.f);
            int idx = (pl * NLAT + i) * MS + (K - 1);
            float P0 = P0s[idx];
            float P2 = P2s[idx];
            float norm = (float)K - cinv * S2K;
            float sm = __fdividef(P0 - cinv * P2, norm);  // MUFU 3
            acc = fmaf(eb_[i], sm, acc);
        }
        redf[tid] = acc;
    }
    __syncthreads();
    if (tid < 64) {
        int b  = tid & 7;
        int pl = tid >> 3;
        out[(size_t)b * N_FULL + p0 + pl] = redf[tid] + redf[tid + 64];
    }
}

// ---------------------------------------------------------------------------
extern "C" void kernel_launch(void* const* d_in, const int* in_sizes, int n_in,
                              void* d_out, int out_size) {
    const float* x   = (const float*)d_in[0];
    const float* ew  = (const float*)d_in[1];
    const float* ebv = (const float*)d_in[2];
    const float* dec = (const float*)d_in[3];
    const float* bw  = (const float*)d_in[4];
    const int*   nb  = (const int*)d_in[5];
    float* out = (float*)d_out;

    encprep_kernel<<<ENC_BLOCKS + PREP_BLOCKS, 256>>>(x, ew, dec);
    main_kernel<<<N_FULL / TILE, 128>>>(bw, nb, ebv, out);
}

// round 10
// speedup vs baseline: 1.0655x; 1.0156x over previous
#include <cuda_runtime.h>

#define N_FULL 50000
#define NLAT 10
#define MU 32
#define BATCH 8
#define TILE 8
#define MS 35               // m-stride per (pl,i) row  (35 ≡ 3 mod 32)
#define ENC_CHUNKS 25
#define ENC_VPC 500         // float4 per chunk (25*500 = 12500 = N/4)
#define ENC_BLOCKS (ENC_CHUNKS * BATCH)     // 200
#define PREP_BLOCKS ((N_FULL + 255) / 256)  // 196
#define WP_BLOCKS ((N_FULL + 255) / 256)    // 196 p-tiles for wcompute

// Scratch (allocation-free rule: __device__ globals)
__device__ float  g_part[ENC_CHUNKS * BATCH * NLAT];  // [chunk][b*10+i] partial dots
__device__ float  g_encoded[BATCH * NLAT];
__device__ float4 g_dect[N_FULL * 4];   // [node][4 x float4]: 10 decoder vals + pad
__device__ float  g_w[NLAT * N_FULL * BATCH];  // cinv, layout [i][p][b] (16MB)

// ---------------------------------------------------------------------------
// Kernel 1 (fused): blocks [0,200) encode split-K partials (no atomics);
// blocks [200,396) transpose decoder into g_dect.
// ---------------------------------------------------------------------------
__global__ __launch_bounds__(256)
void encprep_kernel(const float* __restrict__ x,
                    const float* __restrict__ ew,
                    const float* __restrict__ dec) {
    int bid = blockIdx.x;
    int tid = threadIdx.x;

    if (bid < ENC_BLOCKS) {
        int b     = bid / ENC_CHUNKS;
        int chunk = bid % ENC_CHUNKS;
        int c0    = chunk * ENC_VPC;
        int t0 = tid, t1 = tid + 256;

        const float4* xv = (const float4*)(x + (size_t)b * N_FULL) + c0;
        float4 xa = xv[t0];
        float4 xb = (t1 < ENC_VPC) ? xv[t1] : make_float4(0.f, 0.f, 0.f, 0.f);

        float acc[NLAT];
        #pragma unroll
        for (int i = 0; i < NLAT; i++) {
            const float4* wv = (const float4*)(ew + (size_t)i * N_FULL) + c0;
            float4 wa = wv[t0];
            float4 wb = (t1 < ENC_VPC) ? wv[t1] : make_float4(0.f, 0.f, 0.f, 0.f);
            float s;
            s = xa.x * wa.x;
            s = fmaf(xa.y, wa.y, s);
            s = fmaf(xa.z, wa.z, s);
            s = fmaf(xa.w, wa.w, s);
            s = fmaf(xb.x, wb.x, s);
            s = fmaf(xb.y, wb.y, s);
            s = fmaf(xb.z, wb.z, s);
            s = fmaf(xb.w, wb.w, s);
            acc[i] = s;
        }

        __shared__ float red[8][NLAT];
        #pragma unroll
        for (int i = 0; i < NLAT; i++) {
            float s = acc[i];
            #pragma unroll
            for (int o = 16; o; o >>= 1) s += __shfl_down_sync(0xffffffffu, s, o);
            if ((tid & 31) == 0) red[tid >> 5][i] = s;
        }
        __syncthreads();
        if (tid < NLAT) {
            float s = 0.f;
            #pragma unroll
            for (int w = 0; w < 8; w++) s += red[w][tid];
            g_part[chunk * (BATCH * NLAT) + b * NLAT + tid] = s;
        }
    } else {
        int j = (bid - ENC_BLOCKS) * 256 + tid;
        if (j >= N_FULL) return;
        float d[NLAT];
        #pragma unroll
        for (int i = 0; i < NLAT; i++) d[i] = dec[(size_t)i * N_FULL + j];
        g_dect[j * 4 + 0] = make_float4(d[0], d[1], d[2], d[3]);
        g_dect[j * 4 + 1] = make_float4(d[4], d[5], d[6], d[7]);
        g_dect[j * 4 + 2] = make_float4(d[8], d[9], 0.f, 0.f);
    }
}

// ---------------------------------------------------------------------------
// Kernel 2: wcompute. grid (196, 10), 256 threads. One thread per (i, p).
// Reads bw coalesced along p; computes cinv[b] = (1+e^-t)^2/1024 for 8 b's;
// stores [i][p][b] so main reads it as 32-consecutive-float warps.
// Block (0,0) also publishes the reduced g_encoded.
// ---------------------------------------------------------------------------
__global__ __launch_bounds__(256)
void wcompute_kernel(const float* __restrict__ bw,
                     const float* __restrict__ eb) {
    __shared__ float enc_s[BATCH * NLAT];
    int tid = threadIdx.x;
    int i   = blockIdx.y;
    int p   = blockIdx.x * 256 + tid;

    if (tid < BATCH * NLAT) {
        float s = __ldg(&eb[tid - (tid / NLAT) * NLAT]);
        #pragma unroll
        for (int c = 0; c < ENC_CHUNKS; c++)
            s += g_part[c * (BATCH * NLAT) + tid];
        enc_s[tid] = s;
        if (blockIdx.x == 0 && blockIdx.y == 0) g_encoded[tid] = s;
    }
    __syncthreads();

    if (p >= N_FULL) return;

    float t[BATCH];
    #pragma unroll
    for (int b = 0; b < BATCH; b++) t[b] = 0.f;
    #pragma unroll
    for (int k = 0; k < NLAT; k++) {
        float v = __ldg(&bw[(size_t)(i * NLAT + k) * N_FULL + p]);
        #pragma unroll
        for (int b = 0; b < BATCH; b++)
            t[b] = fmaf(enc_s[b * NLAT + k], v, t[b]);
    }
    float c[BATCH];
    #pragma unroll
    for (int b = 0; b < BATCH; b++) {
        float q = 1.f + __expf(-t[b]);                 // q = 1/w
        c[b] = fminf(q * q * (1.f / 1024.f), 1e12f);   // cinv = 1/(32w)^2
    }
    float4* dst = (float4*)&g_w[((size_t)i * N_FULL + p) * BATCH];
    dst[0] = make_float4(c[0], c[1], c[2], c[3]);
    dst[1] = make_float4(c[4], c[5], c[6], c[7]);
}

// ---------------------------------------------------------------------------
// Kernel 3: main. Per block: TILE=8 nodes, 128 threads.
//   E: read g_encoded (80 floats)
//   A: stage neighbour indices via int4
//   B: cooperative gather — 3 lanes share one 64B decoder row (1 L1 line)
//   C: prefix sums over m (register-batched rounds of 8)
//   D: per (node,b,i-half): cinv from g_w (coalesced), K via rsqrt, closed form
// ---------------------------------------------------------------------------
__global__ __launch_bounds__(128)
void main_kernel(const int*  __restrict__ nb,
                 float*      __restrict__ out) {
    __shared__ float enc_s[BATCH * NLAT];
    __shared__ int   nbs[TILE * MU];          // 1KB; reused as float[128] for D-reduce
    __shared__ float P0s[TILE * NLAT * MS];   // [pl][i][m], m-stride 35
    __shared__ float P2s[TILE * NLAT * MS];

    int tid = threadIdx.x;
    int p0  = blockIdx.x * TILE;

    // ---- Phase E: read reduced encode ----
    if (tid < BATCH * NLAT) enc_s[tid] = g_encoded[tid];

    // ---- Phase A: stage indices (256 ints = 64 int4) ----
    if (tid < TILE * MU / 4)
        ((int4*)nbs)[tid] = __ldg(&((const int4*)(nb + (size_t)p0 * MU))[tid]);
    __syncthreads();

    // ---- Phase B: cooperative gather (3 lanes per index -> 1 line) ----
    #pragma unroll
    for (int it = 0; it < TILE * MU * 3 / 128; it++) {   // 6 iters
        int t = it * 128 + tid;
        int s = t / 3;                 // index id (0..255)
        int chunk = t - s * 3;         // 0,1,2
        int j = nbs[s];
        float4 v = g_dect[j * 4 + chunk];
        int base = (s >> 5) * (NLAT * MS) + (s & 31) + chunk * (4 * MS);
        P0s[base]          = v.x;
        P0s[base + MS]     = v.y;
        if (chunk != 2) {
            P0s[base + 2 * MS] = v.z;
            P0s[base + 3 * MS] = v.w;
        }
    }
    __syncthreads();

    // ---- Phase C: prefix sums, register-batched in rounds of 8 (80 rows) ----
    if (tid < TILE * NLAT) {
        int base = tid * MS;
        float s0 = 0.f, s2 = 0.f;
        #pragma unroll
        for (int h = 0; h < 4; h++) {
            float g[8];
            #pragma unroll
            for (int q = 0; q < 8; q++) g[q] = P0s[base + h * 8 + q];  // batched
            #pragma unroll
            for (int q = 0; q < 8; q++) {
                int m = h * 8 + q;
                s0 += g[q];
                s2 = fmaf(g[q], (float)(m * m), s2);
                P0s[base + m] = s0;
                P2s[base + m] = s2;
            }
        }
    }
    __syncthreads();

    // ---- Phase D: 128 threads = 8 nodes x 8 b x 2 i-halves ----
    float* redf = (float*)nbs;
    {
        int b    = tid & 7;
        int pl   = (tid >> 3) & 7;
        int half = tid >> 6;
        int p    = p0 + pl;
        float eb_[NLAT];
        #pragma unroll
        for (int k = 0; k < NLAT; k++) eb_[k] = enc_s[b * NLAT + k];

        float acc = 0.f;
        #pragma unroll
        for (int ii = 0; ii < 5; ii++) {
            int i = half * 5 + ii;
            // coalesced: warp covers 32 consecutive floats of g_w[i][p0..][b]
            float cinv = __ldg(&g_w[((size_t)i * N_FULL + p) * BATCH + b]);
            float u = rsqrtf(cinv);                       // u = 32w
            int K = min(MU, (int)u + 1);                  // #window terms
            float S2K = (float)((K - 1) * K * (2 * K - 1)) * (1.f / 6.f);
            int idx = (pl * NLAT + i) * MS + (K - 1);
            float P0 = P0s[idx];
            float P2 = P2s[idx];
            float norm = (float)K - cinv * S2K;
            float sm = __fdividef(P0 - cinv * P2, norm);
            acc = fmaf(eb_[i], sm, acc);
        }
        redf[tid] = acc;
    }
    __syncthreads();
    if (tid < 64) {
        int b  = tid & 7;
        int pl = tid >> 3;
        out[(size_t)b * N_FULL + p0 + pl] = redf[tid] + redf[tid + 64];
    }
}

// ---------------------------------------------------------------------------
extern "C" void kernel_launch(void* const* d_in, const int* in_sizes, int n_in,
                              void* d_out, int out_size) {
    const float* x   = (const float*)d_in[0];
    const float* ew  = (const float*)d_in[1];
    const float* ebv = (const float*)d_in[2];
    const float* dec = (const float*)d_in[3];
    const float* bw  = (const float*)d_in[4];
    const int*   nb  = (const int*)d_in[5];
    float* out = (float*)d_out;

    encprep_kernel<<<ENC_BLOCKS + PREP_BLOCKS, 256>>>(x, ew, dec);
    wcompute_kernel<<<dim3(WP_BLOCKS, NLAT), 256>>>(bw, ebv);
    main_kernel<<<N_FULL / TILE, 128>>>(nb, out);
}